// round 3
// baseline (speedup 1.0000x reference)
#include <cuda_runtime.h>

// Sinkhorn distance, N=M=4096, D=2, P=1, eps=0.1, 50 iterations.
// Persistent kernel. Gauss-Seidel passes synchronized with fine-grained
// per-group producer/consumer flags (no global barrier), double-buffered u/v.
// Math in log2 domain pre-scaled by log2(e)/eps; packed f32x2 inner loop.

#define NN      4096
#define NCTA    128
#define NT      1024
#define NWARP   32
#define RPC     32          // rows (or cols) owned per CTA
#define PPW     64          // float2-pairs per warp per pass
#define ITERS   50
#define NGRP    32          // flag groups (4 CTAs each)
#define WPG     128         // warp-arrivals per group per iter (32 warps * 4 CTAs)

#define SCALEF      14.426950408889634f    // log2(e)/eps
#define INV_SCALEF  0.06931471805599453f   // eps*ln(2)
#define LMU2        (-11.9999409054f)      // log2(1/4096 + 1e-8)

typedef unsigned long long ull;

__device__ float g_u[2][NN];
__device__ float g_v[2][NN];
__device__ unsigned int g_ucnt[NGRP];
__device__ unsigned int g_vcnt[NGRP];
__device__ float g_cost[NCTA];
__device__ unsigned int g_costcnt;

__device__ __forceinline__ float ex2f(float v) {
    float r; asm("ex2.approx.f32 %0, %1;" : "=f"(r) : "f"(v)); return r;
}
__device__ __forceinline__ float lg2f(float v) {
    float r; asm("lg2.approx.f32 %0, %1;" : "=f"(r) : "f"(v)); return r;
}
__device__ __forceinline__ ull fadd2(ull a, ull b) {
    ull r; asm("add.rn.f32x2 %0, %1, %2;" : "=l"(r) : "l"(a), "l"(b)); return r;
}
__device__ __forceinline__ ull pk(float lo, float hi) {
    ull r; asm("mov.b64 %0, {%1, %2};" : "=l"(r) : "f"(lo), "f"(hi)); return r;
}
__device__ __forceinline__ void upk(ull v, float& lo, float& hi) {
    asm("mov.b64 {%0, %1}, %2;" : "=f"(lo), "=f"(hi) : "l"(v));
}
__device__ __forceinline__ unsigned int ld_acq(const unsigned int* p) {
    unsigned int v;
    asm volatile("ld.acquire.gpu.global.u32 %0, [%1];" : "=r"(v) : "l"(p));
    return v;
}

__global__ void sk_init_kernel() {
    int t = blockIdx.x * blockDim.x + threadIdx.x;
    if (t < NGRP) { g_ucnt[t] = 0; g_vcnt[t] = 0; }
    if (t == NGRP) g_costcnt = 0;
    for (int i = t; i < NN; i += gridDim.x * blockDim.x) g_v[0][i] = 0.f;
}

// acc += 2^{v - |X0-y0| - |X1-y1|} for a point pair (packed f32x2).
__device__ __forceinline__ void sk_step(ull& acc, float4 c, float2 vp, ull X0p, ull X1p) {
    ull d0 = fadd2(X0p, pk(c.x, c.y));
    ull d1 = fadd2(X1p, pk(c.z, c.w));
    float d0l, d0h, d1l, d1h;
    upk(d0, d0l, d0h);
    upk(d1, d1l, d1h);
    float sl = -fabsf(d0l) - fabsf(d1l);
    float sh = -fabsf(d0h) - fabsf(d1h);
    ull arg = fadd2(pk(vp.x, vp.y), pk(sl, sh));
    float al, ah;
    upk(arg, al, ah);
    acc = fadd2(acc, pk(ex2f(al), ex2f(ah)));
}

__global__ void __launch_bounds__(NT, 1)
sk_persist_kernel(const float* __restrict__ x, const float* __restrict__ y,
                  float* __restrict__ out) {
    extern __shared__ float4 smem_raw[];
    float4* sxc = smem_raw;                 // 32KB {-x0a,-x0b,-x1a,-x1b} pair-interleaved
    float4* syc = smem_raw + NN / 2;        // 32KB
    float*  su  = (float*)(smem_raw + NN);  // 16KB
    float*  sv  = su + NN;                  // 16KB
    __shared__ float part[2][NWARP * 33];
    __shared__ float red[NWARP];

    const int tid  = threadIdx.x;
    const int lane = tid & 31;
    const int wid  = tid >> 5;
    const int cta  = blockIdx.x;
    const int rbase = cta * RPC;
    const int grp  = cta >> 2;

    // Prologue: negated, pre-scaled coords (immutable).
    for (int p = tid; p < NN / 2; p += NT) {
        float4 r = ((const float4*)x)[p];
        sxc[p] = make_float4(-SCALEF * r.x, -SCALEF * r.z, -SCALEF * r.y, -SCALEF * r.w);
        float4 q = ((const float4*)y)[p];
        syc[p] = make_float4(-SCALEF * q.x, -SCALEF * q.z, -SCALEF * q.y, -SCALEF * q.w);
    }
    __syncthreads();

    const int myrow = rbase + lane;
    const float X0 = x[2 * myrow] * SCALEF;
    const float X1 = x[2 * myrow + 1] * SCALEF;
    const float Y0 = y[2 * myrow] * SCALEF;
    const float Y1 = y[2 * myrow + 1] * SCALEF;
    const ull X0p = pk(X0, X0), X1p = pk(X1, X1);
    const ull Y0p = pk(Y0, Y0), Y1p = pk(Y1, Y1);

    for (int it = 0; it < ITERS; ++it) {
        const int ub = it & 1;              // u buffer written this iter
        const int vb = it & 1;              // v buffer read this iter
        const int vwb = (it + 1) & 1;       // v buffer written this iter

        // ===== u pass: u_i = LMU2 - log2( sum_j 2^{v_j - C_ij} ) =====
        {   // wait for v-chunk `wid` (CTAs 4*wid..4*wid+3, iter it-1)
            const unsigned int tgt = (unsigned int)(WPG * it);
            while (ld_acq(&g_vcnt[wid]) < tgt) { }
            // stage chunk into private smem slice
            ((float4*)sv)[wid * 32 + lane] =
                __ldcg(((const float4*)g_v[vb]) + wid * 32 + lane);
            __syncwarp();

            const float4* cb = syc + wid * PPW;
            const float2* vp = (const float2*)sv + wid * PPW;
            ull a0 = 0, a1 = 0, a2 = 0, a3 = 0;
            #pragma unroll 4
            for (int k = 0; k < PPW; k += 4) {
                sk_step(a0, cb[k + 0], vp[k + 0], X0p, X1p);
                sk_step(a1, cb[k + 1], vp[k + 1], X0p, X1p);
                sk_step(a2, cb[k + 2], vp[k + 2], X0p, X1p);
                sk_step(a3, cb[k + 3], vp[k + 3], X0p, X1p);
            }
            ull t = fadd2(fadd2(a0, a1), fadd2(a2, a3));
            float tl, th; upk(t, tl, th);
            part[0][wid * 33 + lane] = tl + th;
        }
        __syncthreads();
        {   // warp `wid` reduces row `wid` (transposed, conflict-free)
            float pv = part[0][lane * 33 + wid];
            #pragma unroll
            for (int o = 16; o > 0; o >>= 1) pv += __shfl_xor_sync(0xffffffffu, pv, o);
            if (lane == 0) {
                __stcg(&g_u[ub][rbase + wid], LMU2 - lg2f(pv));
                __threadfence();
                atomicAdd(&g_ucnt[grp], 1u);   // fire-and-forget release
            }
        }

        // ===== v pass: v_j = LMU2 - log2( sum_i 2^{u_i - C_ij} ) =====
        {
            const unsigned int tgt = (unsigned int)(WPG * (it + 1));
            while (ld_acq(&g_ucnt[wid]) < tgt) { }
            ((float4*)su)[wid * 32 + lane] =
                __ldcg(((const float4*)g_u[ub]) + wid * 32 + lane);
            __syncwarp();

            const float4* cb = sxc + wid * PPW;
            const float2* up = (const float2*)su + wid * PPW;
            ull a0 = 0, a1 = 0, a2 = 0, a3 = 0;
            #pragma unroll 4
            for (int k = 0; k < PPW; k += 4) {
                sk_step(a0, cb[k + 0], up[k + 0], Y0p, Y1p);
                sk_step(a1, cb[k + 1], up[k + 1], Y0p, Y1p);
                sk_step(a2, cb[k + 2], up[k + 2], Y0p, Y1p);
                sk_step(a3, cb[k + 3], up[k + 3], Y0p, Y1p);
            }
            ull t = fadd2(fadd2(a0, a1), fadd2(a2, a3));
            float tl, th; upk(t, tl, th);
            part[1][wid * 33 + lane] = tl + th;
        }
        __syncthreads();
        {
            float pv = part[1][lane * 33 + wid];
            #pragma unroll
            for (int o = 16; o > 0; o >>= 1) pv += __shfl_xor_sync(0xffffffffu, pv, o);
            if (lane == 0) {
                __stcg(&g_v[vwb][rbase + wid], LMU2 - lg2f(pv));
                __threadfence();
                atomicAdd(&g_vcnt[grp], 1u);
            }
        }
    }

    // ===== final: pi = 2^{u_i + v_j - C_ij}, C, cost =====
    // Need the full final v (buffer (ITERS)&1 = 0) and own-CTA final u (buffer 1).
    {
        const unsigned int tgt = (unsigned int)(WPG * ITERS);
        for (;;) {
            bool ok = (lane >= NGRP) || (ld_acq(&g_vcnt[lane]) >= tgt);
            if (__all_sync(0xffffffffu, ok)) break;
        }
    }
    for (int q = tid; q < NN / 4; q += NT)
        ((float4*)sv)[q] = __ldcg(((const float4*)g_v[ITERS & 1]) + q);
    if (tid < RPC) su[rbase + tid] = __ldcg(&g_u[(ITERS - 1) & 1][rbase + tid]);
    __syncthreads();

    const size_t NM = (size_t)NN * NN;
    float* pi_out = out + 1;
    float* c_out  = out + 1 + NM;

    float cacc = 0.f;
    for (int r = 0; r < RPC; ++r) {
        const int i = rbase + r;
        const float Xa = x[2 * i] * SCALEF;
        const float Xb = x[2 * i + 1] * SCALEF;
        const float ui = su[i];
        const size_t off = (size_t)i * NN;
        for (int q = tid; q < NN / 4; q += NT) {
            float4 ca = syc[2 * q];
            float4 cb = syc[2 * q + 1];
            float4 v4 = ((const float4*)sv)[q];
            float ct0 = fabsf(Xa + ca.x) + fabsf(Xb + ca.z);
            float ct1 = fabsf(Xa + ca.y) + fabsf(Xb + ca.w);
            float ct2 = fabsf(Xa + cb.x) + fabsf(Xb + cb.z);
            float ct3 = fabsf(Xa + cb.y) + fabsf(Xb + cb.w);
            float p0 = ex2f(ui + v4.x - ct0);
            float p1 = ex2f(ui + v4.y - ct1);
            float p2 = ex2f(ui + v4.z - ct2);
            float p3 = ex2f(ui + v4.w - ct3);
            float c0 = ct0 * INV_SCALEF, c1 = ct1 * INV_SCALEF;
            float c2 = ct2 * INV_SCALEF, c3 = ct3 * INV_SCALEF;
            const size_t b = off + 4 * (size_t)q;
            pi_out[b + 0] = p0; pi_out[b + 1] = p1; pi_out[b + 2] = p2; pi_out[b + 3] = p3;
            c_out[b + 0]  = c0; c_out[b + 1]  = c1; c_out[b + 2]  = c2; c_out[b + 3]  = c3;
            cacc += p0 * c0 + p1 * c1;
            cacc += p2 * c2 + p3 * c3;
        }
    }
    #pragma unroll
    for (int o = 16; o > 0; o >>= 1) cacc += __shfl_xor_sync(0xffffffffu, cacc, o);
    if (lane == 0) red[wid] = cacc;
    __syncthreads();
    if (wid == 0) {
        float s = red[lane];
        #pragma unroll
        for (int o = 16; o > 0; o >>= 1) s += __shfl_xor_sync(0xffffffffu, s, o);
        if (lane == 0) {
            __stcg(&g_cost[cta], s);
            __threadfence();
            unsigned int old = atomicAdd(&g_costcnt, 1u);
            if (old == NCTA - 1) {          // last CTA: deterministic final sum
                __threadfence();
                float t = 0.f;
                for (int b = 0; b < NCTA; ++b) t += __ldcg(&g_cost[b]);
                out[0] = t;                 // cost ** (1/P), P = 1
            }
        }
    }
}

extern "C" void kernel_launch(void* const* d_in, const int* in_sizes, int n_in,
                              void* d_out, int out_size) {
    (void)in_sizes; (void)n_in; (void)out_size;
    const float* x = (const float*)d_in[0];
    const float* y = (const float*)d_in[1];
    float* out = (float*)d_out;

    const size_t smem = (size_t)NN * sizeof(float4) + 2 * NN * sizeof(float); // 96KB
    cudaFuncSetAttribute(sk_persist_kernel,
                         cudaFuncAttributeMaxDynamicSharedMemorySize, (int)smem);

    sk_init_kernel<<<8, 512>>>();
    sk_persist_kernel<<<NCTA, NT, smem>>>(x, y, out);
}

// round 7
// speedup vs baseline: 1.2829x; 1.2829x over previous
#include <cuda_runtime.h>

// Sinkhorn distance, N=M=4096, D=2, P=1, eps=0.1, 50 iterations.
// Persistent kernel. Dataflow sync: one st.release flag per CTA per half-pass;
// consumer warps acquire only their 4 producer CTAs' flags. No atomics in the
// iteration loop. Double-buffered u/v. Packed f32x2 inner loop, log2 domain.

#define NN      4096
#define NCTA    128
#define NT      1024
#define NWARP   32
#define RPC     32          // rows (or cols) owned per CTA
#define PPW     64          // float2-pairs per warp per pass
#define ITERS   50

#define SCALEF      14.426950408889634f    // log2(e)/eps
#define INV_SCALEF  0.06931471805599453f   // eps*ln(2)
#define LMU2        (-11.9999409054f)      // log2(1/4096 + 1e-8)

typedef unsigned long long ull;

struct __align__(128) Flag { unsigned int f; unsigned int pad[31]; };

__device__ float g_u[2][NN];
__device__ float g_v[2][NN];
__device__ Flag g_uflag[NCTA];
__device__ Flag g_vflag[NCTA];
__device__ float g_cost[NCTA];
__device__ unsigned int g_costcnt;

__device__ __forceinline__ float ex2f(float v) {
    float r; asm("ex2.approx.f32 %0, %1;" : "=f"(r) : "f"(v)); return r;
}
__device__ __forceinline__ float lg2f(float v) {
    float r; asm("lg2.approx.f32 %0, %1;" : "=f"(r) : "f"(v)); return r;
}
__device__ __forceinline__ ull fadd2(ull a, ull b) {
    ull r; asm("add.rn.f32x2 %0, %1, %2;" : "=l"(r) : "l"(a), "l"(b)); return r;
}
__device__ __forceinline__ ull pk(float lo, float hi) {
    ull r; asm("mov.b64 %0, {%1, %2};" : "=l"(r) : "f"(lo), "f"(hi)); return r;
}
__device__ __forceinline__ void upk(ull v, float& lo, float& hi) {
    asm("mov.b64 {%0, %1}, %2;" : "=f"(lo), "=f"(hi) : "l"(v));
}
__device__ __forceinline__ unsigned int ld_acq(const unsigned int* p) {
    unsigned int v;
    asm volatile("ld.acquire.gpu.global.u32 %0, [%1];" : "=r"(v) : "l"(p));
    return v;
}
__device__ __forceinline__ void st_rel(unsigned int* p, unsigned int v) {
    asm volatile("st.release.gpu.global.u32 [%0], %1;" :: "l"(p), "r"(v) : "memory");
}

__global__ void sk_init_kernel() {
    int t = blockIdx.x * blockDim.x + threadIdx.x;
    if (t < NCTA) { g_uflag[t].f = 0; g_vflag[t].f = 0; }
    if (t == NCTA) g_costcnt = 0;
    for (int i = t; i < NN; i += gridDim.x * blockDim.x) g_v[0][i] = 0.f;
}

// acc += 2^{v - |X0-y0| - |X1-y1|} for a point pair (packed f32x2).
__device__ __forceinline__ void sk_step(ull& acc, float4 c, float2 vp, ull X0p, ull X1p) {
    ull d0 = fadd2(X0p, pk(c.x, c.y));
    ull d1 = fadd2(X1p, pk(c.z, c.w));
    float d0l, d0h, d1l, d1h;
    upk(d0, d0l, d0h);
    upk(d1, d1l, d1h);
    float sl = -fabsf(d0l) - fabsf(d1l);
    float sh = -fabsf(d0h) - fabsf(d1h);
    ull arg = fadd2(pk(vp.x, vp.y), pk(sl, sh));
    float al, ah;
    upk(arg, al, ah);
    acc = fadd2(acc, pk(ex2f(al), ex2f(ah)));
}

__global__ void __launch_bounds__(NT, 1)
sk_persist_kernel(const float* __restrict__ x, const float* __restrict__ y,
                  float* __restrict__ out) {
    extern __shared__ float4 smem_raw[];
    float4* sxc = smem_raw;                 // 32KB {-x0a,-x0b,-x1a,-x1b} pair-interleaved
    float4* syc = smem_raw + NN / 2;        // 32KB
    float*  su  = (float*)(smem_raw + NN);  // 16KB
    float*  sv  = su + NN;                  // 16KB
    __shared__ float part[NWARP * 33];
    __shared__ float red[NWARP];

    const int tid  = threadIdx.x;
    const int lane = tid & 31;
    const int wid  = tid >> 5;
    const int cta  = blockIdx.x;
    const int rbase = cta * RPC;

    for (int p = tid; p < NN / 2; p += NT) {
        float4 r = ((const float4*)x)[p];
        sxc[p] = make_float4(-SCALEF * r.x, -SCALEF * r.z, -SCALEF * r.y, -SCALEF * r.w);
        float4 q = ((const float4*)y)[p];
        syc[p] = make_float4(-SCALEF * q.x, -SCALEF * q.z, -SCALEF * q.y, -SCALEF * q.w);
    }
    __syncthreads();

    const int myrow = rbase + lane;
    const float X0 = x[2 * myrow] * SCALEF;
    const float X1 = x[2 * myrow + 1] * SCALEF;
    const float Y0 = y[2 * myrow] * SCALEF;
    const float Y1 = y[2 * myrow + 1] * SCALEF;
    const ull X0p = pk(X0, X0), X1p = pk(X1, X1);
    const ull Y0p = pk(Y0, Y0), Y1p = pk(Y1, Y1);

    const int chunk4 = wid * 32 + lane;     // float4 index of this lane's stage slot
    const int pidx   = (wid << 2) + (lane & 3);  // producer CTA polled by lanes 0-3

    for (int it = 0; it < ITERS; ++it) {
        // ===== u pass: u_i = LMU2 - log2( sum_j 2^{v_j - C_ij} ) =====
        // wait for v chunk `wid` (producers: CTAs 4wid..4wid+3, stamp >= it)
        if (lane < 4) { while (ld_acq(&g_vflag[pidx].f) < (unsigned int)it) { } }
        __syncwarp();
        ((float4*)sv)[chunk4] = __ldcg(((const float4*)g_v[it & 1]) + chunk4);
        __syncwarp();
        {
            const float4* cb = syc + wid * PPW;
            const float2* vp = (const float2*)sv + wid * PPW;
            ull a0 = 0, a1 = 0, a2 = 0, a3 = 0;
            #pragma unroll 4
            for (int k = 0; k < PPW; k += 4) {
                sk_step(a0, cb[k + 0], vp[k + 0], X0p, X1p);
                sk_step(a1, cb[k + 1], vp[k + 1], X0p, X1p);
                sk_step(a2, cb[k + 2], vp[k + 2], X0p, X1p);
                sk_step(a3, cb[k + 3], vp[k + 3], X0p, X1p);
            }
            ull t = fadd2(fadd2(a0, a1), fadd2(a2, a3));
            float tl, th; upk(t, tl, th);
            part[wid * 33 + lane] = tl + th;
        }
        __syncthreads();
        {   // warp `wid` reduces row rbase+wid (transposed, conflict-free)
            float pv = part[lane * 33 + wid];
            #pragma unroll
            for (int o = 16; o > 0; o >>= 1) pv += __shfl_xor_sync(0xffffffffu, pv, o);
            if (lane == 0) __stcg(&g_u[it & 1][rbase + wid], LMU2 - lg2f(pv));
        }
        __syncthreads();
        if (tid == 0) st_rel(&g_uflag[cta].f, (unsigned int)(it + 1));

        // ===== v pass: v_j = LMU2 - log2( sum_i 2^{u_i - C_ij} ) =====
        if (lane < 4) { while (ld_acq(&g_uflag[pidx].f) < (unsigned int)(it + 1)) { } }
        __syncwarp();
        ((float4*)su)[chunk4] = __ldcg(((const float4*)g_u[it & 1]) + chunk4);
        __syncwarp();
        {
            const float4* cb = sxc + wid * PPW;
            const float2* up = (const float2*)su + wid * PPW;
            ull a0 = 0, a1 = 0, a2 = 0, a3 = 0;
            #pragma unroll 4
            for (int k = 0; k < PPW; k += 4) {
                sk_step(a0, cb[k + 0], up[k + 0], Y0p, Y1p);
                sk_step(a1, cb[k + 1], up[k + 1], Y0p, Y1p);
                sk_step(a2, cb[k + 2], up[k + 2], Y0p, Y1p);
                sk_step(a3, cb[k + 3], up[k + 3], Y0p, Y1p);
            }
            ull t = fadd2(fadd2(a0, a1), fadd2(a2, a3));
            float tl, th; upk(t, tl, th);
            part[wid * 33 + lane] = tl + th;
        }
        __syncthreads();
        {
            float pv = part[lane * 33 + wid];
            #pragma unroll
            for (int o = 16; o > 0; o >>= 1) pv += __shfl_xor_sync(0xffffffffu, pv, o);
            if (lane == 0) __stcg(&g_v[(it + 1) & 1][rbase + wid], LMU2 - lg2f(pv));
        }
        __syncthreads();
        if (tid == 0) st_rel(&g_vflag[cta].f, (unsigned int)(it + 1));
    }

    // ===== final: pi = 2^{u_i + v_j - C_ij}, C, cost =====
    // su already holds the final u (staged during v-pass 49 from g_u[1]).
    // Stage final v = g_v[ITERS & 1] = g_v[0] after acquiring producer stamps.
    if (lane < 4) { while (ld_acq(&g_vflag[pidx].f) < (unsigned int)ITERS) { } }
    __syncwarp();
    ((float4*)sv)[chunk4] = __ldcg(((const float4*)g_v[ITERS & 1]) + chunk4);
    __syncthreads();

    const size_t NM = (size_t)NN * NN;
    float* pi_out = out + 1;
    float* c_out  = out + 1 + NM;

    float cacc = 0.f;
    for (int r = 0; r < RPC; ++r) {
        const int i = rbase + r;
        const float Xa = x[2 * i] * SCALEF;
        const float Xb = x[2 * i + 1] * SCALEF;
        const float ui = su[i];
        const size_t off = (size_t)i * NN;
        for (int q = tid; q < NN / 4; q += NT) {
            float4 ca = syc[2 * q];
            float4 cb = syc[2 * q + 1];
            float4 v4 = ((const float4*)sv)[q];
            float ct0 = fabsf(Xa + ca.x) + fabsf(Xb + ca.z);
            float ct1 = fabsf(Xa + ca.y) + fabsf(Xb + ca.w);
            float ct2 = fabsf(Xa + cb.x) + fabsf(Xb + cb.z);
            float ct3 = fabsf(Xa + cb.y) + fabsf(Xb + cb.w);
            float p0 = ex2f(ui + v4.x - ct0);
            float p1 = ex2f(ui + v4.y - ct1);
            float p2 = ex2f(ui + v4.z - ct2);
            float p3 = ex2f(ui + v4.w - ct3);
            float c0 = ct0 * INV_SCALEF, c1 = ct1 * INV_SCALEF;
            float c2 = ct2 * INV_SCALEF, c3 = ct3 * INV_SCALEF;
            const size_t b = off + 4 * (size_t)q;
            pi_out[b + 0] = p0; pi_out[b + 1] = p1; pi_out[b + 2] = p2; pi_out[b + 3] = p3;
            c_out[b + 0]  = c0; c_out[b + 1]  = c1; c_out[b + 2]  = c2; c_out[b + 3]  = c3;
            cacc += p0 * c0 + p1 * c1;
            cacc += p2 * c2 + p3 * c3;
        }
    }
    #pragma unroll
    for (int o = 16; o > 0; o >>= 1) cacc += __shfl_xor_sync(0xffffffffu, cacc, o);
    if (lane == 0) red[wid] = cacc;
    __syncthreads();
    if (wid == 0) {
        float s = red[lane];
        #pragma unroll
        for (int o = 16; o > 0; o >>= 1) s += __shfl_xor_sync(0xffffffffu, s, o);
        if (lane == 0) {
            __stcg(&g_cost[cta], s);
            __threadfence();
            unsigned int old = atomicAdd(&g_costcnt, 1u);
            if (old == NCTA - 1) {          // last CTA: deterministic final sum
                __threadfence();
                float t = 0.f;
                for (int b = 0; b < NCTA; ++b) t += __ldcg(&g_cost[b]);
                out[0] = t;                 // cost ** (1/P), P = 1
            }
        }
    }
}

extern "C" void kernel_launch(void* const* d_in, const int* in_sizes, int n_in,
                              void* d_out, int out_size) {
    (void)in_sizes; (void)n_in; (void)out_size;
    const float* x = (const float*)d_in[0];
    const float* y = (const float*)d_in[1];
    float* out = (float*)d_out;

    const size_t smem = (size_t)NN * sizeof(float4) + 2 * NN * sizeof(float); // 96KB
    cudaFuncSetAttribute(sk_persist_kernel,
                         cudaFuncAttributeMaxDynamicSharedMemorySize, (int)smem);

    sk_init_kernel<<<8, 512>>>();
    sk_persist_kernel<<<NCTA, NT, smem>>>(x, y, out);
}